// round 17
// baseline (speedup 1.0000x reference)
#include <cuda_runtime.h>
#include <cuda_bf16.h>
#include <mma.h>
#include <cstdint>

using namespace nvcuda;

typedef unsigned long long u64;
typedef unsigned int u32;

#define CB 2048
#define CT 512
#define CH 32

// Scratch: raw gate preactivations (no bias), xg[m*128 + g], m = b*CT + t.
// +CT rows padding so K2's deep prefetch never reads OOB.
__device__ float g_xg[((size_t)CB * CT + CT) * 128];

// ---------------- f32x2 helpers ----------------
__device__ __forceinline__ u64 ffma2(u64 a, u64 b, u64 c) {
    u64 d;
    asm("fma.rn.f32x2 %0, %1, %2, %3;" : "=l"(d) : "l"(a), "l"(b), "l"(c));
    return d;
}
__device__ __forceinline__ u64 addx2(u64 a, u64 b) {
    u64 d;
    asm("add.rn.f32x2 %0, %1, %2;" : "=l"(d) : "l"(a), "l"(b));
    return d;
}
__device__ __forceinline__ u64 pack2(float lo, float hi) {
    u64 d;
    asm("mov.b64 %0, {%1, %2};" : "=l"(d) : "f"(lo), "f"(hi));
    return d;
}
__device__ __forceinline__ float2 unpack2(u64 v) {
    float2 r;
    asm("mov.b64 {%0, %1}, %2;" : "=f"(r.x), "=f"(r.y) : "l"(v));
    return r;
}
__device__ __forceinline__ u32 bfpair(float hi_, float lo_) {
    u32 d;
    asm("cvt.rn.bf16x2.f32 %0, %1, %2;" : "=r"(d) : "f"(hi_), "f"(lo_));
    return d;
}

// Split a float4 into bf16-hi pairs and bf16-lo (residual) pairs.
__device__ __forceinline__ void bf16split(float4 v, u32& h01, u32& h23,
                                          u32& l01, u32& l23) {
    h01 = bfpair(v.y, v.x);
    float q0 = v.x - __uint_as_float(h01 << 16);
    float q1 = v.y - __uint_as_float(h01 & 0xFFFF0000u);
    l01 = bfpair(q1, q0);
    h23 = bfpair(v.w, v.z);
    float q2 = v.z - __uint_as_float(h23 << 16);
    float q3 = v.w - __uint_as_float(h23 & 0xFFFF0000u);
    l23 = bfpair(q3, q2);
}

// ---------------------------------------------------------------------------
// K1: xg GEMM on tensor cores (wmma bf16, split precision).  (R14, ~286us)
//   C[1M x 128] = A[1M x 192] x B[192 x 128]
//   A = [xh | xl | xh] (row-major),  B = [Wh ; Wh ; Wl] (col-major smem).
// Block: 256 thr (8 warps), 8 tiles of 128 rows. B staged once per block.
// Warp (wm = w>>2, wn = w&3): 4 m-tiles x 2 n-tiles of 16x16, 12 k-steps.
// Epilogue: store_matrix_sync straight to global f32 scratch (bias in K2).
// ---------------------------------------------------------------------------
#define ASTR 208   // bf16 elems per A row (192 + 16 pad)
#define BSTR 208   // bf16 elems per B column
#define K1T  8

#define SM_A 0
#define SM_B (128 * ASTR * 2)
#define SM_TOT (128 * ASTR * 2 + 128 * BSTR * 2)   // 106,496 B

extern __shared__ char sm1[];

__global__ __launch_bounds__(256, 2) void k1_wmma(
    const float* __restrict__ x, const float* __restrict__ Wih)
{
    __nv_bfloat16* As = (__nv_bfloat16*)(sm1 + SM_A);
    __nv_bfloat16* Bs = (__nv_bfloat16*)(sm1 + SM_B);
    u32* As32 = (u32*)As;
    u32* Bs32 = (u32*)Bs;

    const int tid = threadIdx.x;
    const size_t m0 = (size_t)blockIdx.x * (128 * K1T);

    // ---- Stage B once: Bs[n*BSTR + k] = Bsplit[k][n] (col-major) ----
    {
        const float4* W4 = (const float4*)Wih;
        #pragma unroll
        for (int i = 0; i < 8; i++) {
            int idx = i * 256 + tid;
            int n = idx >> 4, kq = idx & 15;
            u32 h01, h23, l01, l23;
            bf16split(W4[n * 16 + kq], h01, h23, l01, l23);
            int base = n * (BSTR / 2) + 2 * kq;
            Bs32[base]      = h01;  Bs32[base + 1]  = h23;
            Bs32[base + 32] = h01;  Bs32[base + 33] = h23;
            Bs32[base + 64] = l01;  Bs32[base + 65] = l23;
        }
    }

    const float4* x4 = (const float4*)x;

    float4 nxt[8];
    #pragma unroll
    for (int i = 0; i < 8; i++) {
        int idx = i * 256 + tid;
        nxt[i] = x4[(m0 + (idx >> 4)) * 16 + (idx & 15)];
    }

    const int w  = tid >> 5;
    const int wm = w >> 2;
    const int wn = w & 3;

    for (int tl = 0; tl < K1T; tl++) {
        const size_t mt = m0 + (size_t)tl * 128;

        __syncthreads();
        #pragma unroll
        for (int i = 0; i < 8; i++) {
            int idx = i * 256 + tid;
            int r = idx >> 4, kq = idx & 15;
            u32 h01, h23, l01, l23;
            bf16split(nxt[i], h01, h23, l01, l23);
            int base = r * (ASTR / 2) + 2 * kq;
            As32[base]      = h01;  As32[base + 1]  = h23;
            As32[base + 32] = l01;  As32[base + 33] = l23;
            As32[base + 64] = h01;  As32[base + 65] = h23;
        }
        __syncthreads();

        if (tl + 1 < K1T) {
            #pragma unroll
            for (int i = 0; i < 8; i++) {
                int idx = i * 256 + tid;
                nxt[i] = x4[(mt + 128 + (idx >> 4)) * 16 + (idx & 15)];
            }
        }

        wmma::fragment<wmma::accumulator, 16, 16, 16, float> acc[4][2];
        #pragma unroll
        for (int i = 0; i < 4; i++)
            #pragma unroll
            for (int jn = 0; jn < 2; jn++)
                wmma::fill_fragment(acc[i][jn], 0.0f);

        #pragma unroll
        for (int ks = 0; ks < 12; ks++) {
            wmma::fragment<wmma::matrix_a, 16, 16, 16, __nv_bfloat16,
                           wmma::row_major> af[4];
            #pragma unroll
            for (int i = 0; i < 4; i++)
                wmma::load_matrix_sync(
                    af[i], As + (wm * 64 + i * 16) * ASTR + ks * 16, ASTR);
            wmma::fragment<wmma::matrix_b, 16, 16, 16, __nv_bfloat16,
                           wmma::col_major> bf[2];
            #pragma unroll
            for (int jn = 0; jn < 2; jn++)
                wmma::load_matrix_sync(
                    bf[jn], Bs + (wn * 2 + jn) * 16 * BSTR + ks * 16, BSTR);
            #pragma unroll
            for (int i = 0; i < 4; i++)
                #pragma unroll
                for (int jn = 0; jn < 2; jn++)
                    wmma::mma_sync(acc[i][jn], af[i], bf[jn], acc[i][jn]);
        }

        #pragma unroll
        for (int i = 0; i < 4; i++)
            #pragma unroll
            for (int jn = 0; jn < 2; jn++)
                wmma::store_matrix_sync(
                    g_xg + (mt + wm * 64 + (size_t)i * 16) * 128
                         + (wn * 2 + jn) * 16,
                    acc[i][jn], 128, wmma::mem_row_major);
    }
}

// ---------------------------------------------------------------------------
// K2: recurrence with 4-deep prefetch pipeline. Each warp owns 2 batches;
// lane j = unit j; W_hh register-resident gate-paired; h broadcast via
// grouped __shfl_sync. Loads for timestep t+4 are issued at t -> ~4 phases
// (>1200 cyc) of latency cover, turning K2 into a DRAM stream.
// ---------------------------------------------------------------------------
__device__ __forceinline__ float sigmf(float v) {
    return __fdividef(1.f, 1.f + __expf(-v));
}
__device__ __forceinline__ float tanhf_fast(float v) {
    return 1.f - __fdividef(2.f, 1.f + __expf(2.f * v));
}
__device__ __forceinline__ void lstm_cell(float gi, float gf, float gg, float go,
                                          float& c, float& h) {
    float iv = sigmf(gi);
    float fv = sigmf(gf);
    float gv = tanhf_fast(gg);
    float ov = sigmf(go);
    c = fv * c + iv * gv;
    h = ov * tanhf_fast(c);
}

#define K2W 2
#define PF  4   // prefetch depth (timesteps)

__global__ __launch_bounds__(32 * K2W) void k2_rnn(
    const float* __restrict__ Whh, const float* __restrict__ bih,
    const float* __restrict__ bhh, const float* __restrict__ wfc,
    const float* __restrict__ bfc, float* __restrict__ out)
{
    const int tid = threadIdx.x;
    const int j   = tid & 31;
    const int gw  = blockIdx.x * K2W + (tid >> 5);
    const int b0  = gw * 2;

    u64 wif[CH], wgo[CH];
    #pragma unroll
    for (int k = 0; k < CH; k++) {
        wif[k] = pack2(__ldg(&Whh[(0 * CH + j) * CH + k]),
                       __ldg(&Whh[(1 * CH + j) * CH + k]));
        wgo[k] = pack2(__ldg(&Whh[(2 * CH + j) * CH + k]),
                       __ldg(&Whh[(3 * CH + j) * CH + k]));
    }
    const u64 bif = pack2(bih[j] + bhh[j], bih[32 + j] + bhh[32 + j]);
    const u64 bgo = pack2(bih[64 + j] + bhh[64 + j], bih[96 + j] + bhh[96 + j]);

    float h0 = 0.f, h1 = 0.f, c0 = 0.f, c1 = 0.f;
    const float wfcv = wfc[j];

    // Streaming pointers: row to refill next (starts at t = PF after prologue).
    const float* p0 = g_xg + (size_t)b0 * CT * 128 + j;
    const float* p1 = p0 + (size_t)CT * 128;

    // Circular prefetch buffers: q[phase][gate] per batch.
    float q0[PF][4], q1[PF][4];
    #pragma unroll
    for (int p = 0; p < PF; p++) {
        q0[p][0] = __ldg(p0);  q0[p][1] = __ldg(p0 + 32);
        q0[p][2] = __ldg(p0 + 64);  q0[p][3] = __ldg(p0 + 96);
        q1[p][0] = __ldg(p1);  q1[p][1] = __ldg(p1 + 32);
        q1[p][2] = __ldg(p1 + 64);  q1[p][3] = __ldg(p1 + 96);
        p0 += 128;  p1 += 128;
    }

    for (int tb = 0; tb < CT; tb += PF) {
        #pragma unroll
        for (int ph = 0; ph < PF; ph++) {
            // snapshot this phase's gates
            float xi0 = q0[ph][0], xf0 = q0[ph][1], xg0 = q0[ph][2], xo0 = q0[ph][3];
            float xi1 = q1[ph][0], xf1 = q1[ph][1], xg1 = q1[ph][2], xo1 = q1[ph][3];

            // refill this slot for timestep tb + PF + ph (pad rows cover tail)
            q0[ph][0] = __ldg(p0);  q0[ph][1] = __ldg(p0 + 32);
            q0[ph][2] = __ldg(p0 + 64);  q0[ph][3] = __ldg(p0 + 96);
            q1[ph][0] = __ldg(p1);  q1[ph][1] = __ldg(p1 + 32);
            q1[ph][2] = __ldg(p1 + 64);  q1[ph][3] = __ldg(p1 + 96);
            p0 += 128;  p1 += 128;

            u64 a0_if = addx2(pack2(xi0, xf0), bif);
            u64 a0_go = addx2(pack2(xg0, xo0), bgo);
            u64 a1_if = addx2(pack2(xi1, xf1), bif);
            u64 a1_go = addx2(pack2(xg1, xo1), bgo);

            #pragma unroll
            for (int kb = 0; kb < CH; kb += 8) {
                float v0[8], v1[8];
                #pragma unroll
                for (int kk = 0; kk < 8; kk++) {
                    v0[kk] = __shfl_sync(0xffffffffu, h0, kb + kk);
                    v1[kk] = __shfl_sync(0xffffffffu, h1, kb + kk);
                }
                #pragma unroll
                for (int kk = 0; kk < 8; kk++) {
                    u64 d0 = pack2(v0[kk], v0[kk]);
                    u64 d1 = pack2(v1[kk], v1[kk]);
                    a0_if = ffma2(d0, wif[kb + kk], a0_if);
                    a0_go = ffma2(d0, wgo[kb + kk], a0_go);
                    a1_if = ffma2(d1, wif[kb + kk], a1_if);
                    a1_go = ffma2(d1, wgo[kb + kk], a1_go);
                }
            }

            float2 pp0 = unpack2(a0_if);
            float2 pp1 = unpack2(a0_go);
            lstm_cell(pp0.x, pp0.y, pp1.x, pp1.y, c0, h0);
            float2 qq0 = unpack2(a1_if);
            float2 qq1 = unpack2(a1_go);
            lstm_cell(qq0.x, qq0.y, qq1.x, qq1.y, c1, h1);
        }
    }

    float v0 = h0 * wfcv;
    float v1 = h1 * wfcv;
    #pragma unroll
    for (int o = 16; o > 0; o >>= 1) {
        v0 += __shfl_xor_sync(0xffffffffu, v0, o);
        v1 += __shfl_xor_sync(0xffffffffu, v1, o);
    }
    if (j == 0) {
        float bb = bfc[0];
        out[b0]     = v0 + bb;
        out[b0 + 1] = v1 + bb;
    }
}

// ---------------------------------------------------------------------------
extern "C" void kernel_launch(void* const* d_in, const int* in_sizes, int n_in,
                              void* d_out, int out_size)
{
    const float* x   = (const float*)d_in[0];
    const float* Wih = (const float*)d_in[1];
    const float* Whh = (const float*)d_in[2];
    const float* bih = (const float*)d_in[3];
    const float* bhh = (const float*)d_in[4];
    const float* Wfc = (const float*)d_in[5];
    const float* bfc = (const float*)d_in[6];
    float* out = (float*)d_out;

    cudaFuncSetAttribute(k1_wmma, cudaFuncAttributeMaxDynamicSharedMemorySize, SM_TOT);

    k1_wmma<<<(CB * CT) / (128 * K1T), 256, SM_TOT>>>(x, Wih);
    k2_rnn<<<CB / (2 * K2W), 32 * K2W>>>(Whh, bih, bhh, Wfc, bfc, out);
}